// round 15
// baseline (speedup 1.0000x reference)
#include <cuda_runtime.h>
#include <cstdint>

#define EPSV 1e-5f
#define NGRAPH 256
#define MAXM 100096

#define TM 128
#define TN 256
#define BK 32
#define SAS_A 36                          // padded words per A row
#define SAS_B 32                          // compact words per B row + XOR swizzle
#define A_TILE_BYTES (128 * SAS_A * 4)    // 18432
#define B_TILE_BYTES (256 * SAS_B * 4)    // 32768
#define DYN_SMEM (2 * A_TILE_BYTES + 2 * B_TILE_BYTES + 256)

// ---------------- scratch (device globals; no allocations) ----------------
__device__ int g_start[NGRAPH];
__device__ int g_end[NGRAPH];
__device__ __align__(16) float g_scale1[NGRAPH * 512];
__device__ __align__(16) float g_shift1[NGRAPH * 512];
__device__ __align__(16) float g_scale2[NGRAPH * 256];
__device__ __align__(16) float g_shift2[NGRAPH * 256];
__device__ __align__(16) float g_scale3[256];
__device__ __align__(16) float g_shift3[256];
__device__ __align__(16) float g_scale4[NGRAPH * 256];
__device__ __align__(16) float g_shift4[NGRAPH * 256];
__device__ __align__(16) float g_scale5[NGRAPH * 256];
__device__ __align__(16) float g_shift5[NGRAPH * 256];
__device__ __align__(16) float g_part[512 * 512];
__device__ __align__(16) float g_part2[NGRAPH * 4 * 1024];
__device__ __align__(16) unsigned g_Wt[512 * 256];   // tf32, k pair-permuted per 32-block
__device__ __align__(16) float g_s1[(size_t)MAXM * 256];
__device__ __align__(16) float g_s2[(size_t)MAXM * 256];

__device__ __forceinline__ const float* resolve_in(const float* p, int id) {
    if (id == 1) return g_s1;
    if (id == 2) return g_s2;
    return p;
}
__device__ __forceinline__ float* resolve_out(float* p, int id) {
    if (id == 1) return g_s1;
    if (id == 2) return g_s2;
    return p;
}
__device__ __forceinline__ const float* scale_tab(int layer) {
    switch (layer) {
        case 1: return g_scale1;
        case 2: return g_scale2;
        case 3: return g_scale3;
        case 4: return g_scale4;
        default: return g_scale5;
    }
}
__device__ __forceinline__ const float* shift_tab(int layer) {
    switch (layer) {
        case 1: return g_shift1;
        case 2: return g_shift2;
        case 3: return g_shift3;
        case 4: return g_shift4;
        default: return g_shift5;
    }
}
__device__ __forceinline__ float* scale_tab_w(int layer) {
    switch (layer) {
        case 1: return g_scale1;
        case 2: return g_scale2;
        case 3: return g_scale3;
        case 4: return g_scale4;
        default: return g_scale5;
    }
}
__device__ __forceinline__ float* shift_tab_w(int layer) {
    switch (layer) {
        case 1: return g_shift1;
        case 2: return g_shift2;
        case 3: return g_shift3;
        case 4: return g_shift4;
        default: return g_shift5;
    }
}

// ---------------- helpers ----------------
__device__ __forceinline__ uint32_t smem_u32(const void* p) {
    uint32_t a;
    asm("{ .reg .u64 t; cvta.to.shared.u64 t, %1; cvt.u32.u64 %0, t; }" : "=r"(a) : "l"(p));
    return a;
}
__device__ __forceinline__ unsigned f2tf32(float f) {
    unsigned r;
    asm("cvt.rna.tf32.f32 %0, %1;" : "=r"(r) : "f"(f));
    return r;
}
__device__ __forceinline__ void mma8(float c[4], const unsigned a[4], const unsigned b[2]) {
    asm volatile(
        "mma.sync.aligned.m16n8k8.row.col.f32.tf32.tf32.f32 "
        "{%0,%1,%2,%3}, {%4,%5,%6,%7}, {%8,%9}, {%0,%1,%2,%3};\n"
        : "+f"(c[0]), "+f"(c[1]), "+f"(c[2]), "+f"(c[3])
        : "r"(a[0]), "r"(a[1]), "r"(a[2]), "r"(a[3]), "r"(b[0]), "r"(b[1]));
}
__device__ __forceinline__ void cp16(uint32_t dst, const void* src) {
    asm volatile("cp.async.cg.shared.global [%0], [%1], 16;" :: "r"(dst), "l"(src));
}
#define CP_COMMIT() asm volatile("cp.async.commit_group;" ::: "memory")
#define CP_WAIT0()  asm volatile("cp.async.wait_group 0;" ::: "memory")

// permuted position of k-in-stage kl (0..31): pairs (k, k+4) adjacent within 8-groups
__device__ __forceinline__ int kperm(int kl) {
    return (kl & 24) + ((kl & 3) << 1) + ((kl >> 2) & 1);
}

// ---------------- segment bounds ----------------
__global__ void seg_bounds_init() {
    int t = threadIdx.x;
    if (t < NGRAPH) { g_start[t] = 0; g_end[t] = 0; }
}

__global__ void seg_bounds(const int* __restrict__ batch, int n) {
    int i = blockIdx.x * blockDim.x + threadIdx.x;
    if (i >= n) return;
    int g = batch[i];
    if (g < 0 || g >= NGRAPH) return;
    if (i == 0 || batch[i - 1] != g) g_start[g] = i;
    if (i == n - 1 || batch[i + 1] != g) g_end[g] = i + 1;
}

// ---------------- per-graph stats: 4-way split partial + combine ----------------
__global__ void seg_stats_part(const float* xp, int x_id, int dim) {
    const float* __restrict__ x = resolve_in(xp, x_id);
    int g = blockIdx.x, part = blockIdx.y, t = threadIdx.x;
    int s0 = g_start[g], e0 = g_end[g];
    int len = e0 - s0;
    int chunk = (len + 3) >> 2;
    int r0 = s0 + part * chunk;
    int r1 = r0 + chunk; if (r1 > e0) r1 = e0;
    float s = 0.f, q = 0.f;
    for (int r = r0; r < r1; ++r) {
        float v = x[(size_t)r * dim + t];
        s += v;
        q += v * v;
    }
    size_t base = ((size_t)(g * 4 + part)) * 1024;
    g_part2[base + t] = s;
    g_part2[base + 512 + t] = q;
}

__global__ void seg_stats_final(const float* __restrict__ w, const float* __restrict__ b,
                                const float* __restrict__ ms, int layer, int dim) {
    float* __restrict__ scale = scale_tab_w(layer);
    float* __restrict__ shift = shift_tab_w(layer);
    int g = blockIdx.x, t = threadIdx.x;
    float s = 0.f, q = 0.f;
#pragma unroll
    for (int p = 0; p < 4; ++p) {
        size_t base = ((size_t)(g * 4 + p)) * 1024;
        s += g_part2[base + t];
        q += g_part2[base + 512 + t];
    }
    float cnt = fmaxf((float)(g_end[g] - g_start[g]), 1.f);
    float mean = s / cnt;
    float m2 = mean * ms[t];
    float var = q / cnt - 2.f * m2 * mean + m2 * m2;
    float sc = w[t] * rsqrtf(var + EPSV);
    scale[(size_t)g * dim + t] = sc;
    shift[(size_t)g * dim + t] = b[t] - m2 * sc;
}

// ---------------- global stats (gn3) ----------------
__global__ void glob_partial(int x_id, int M) {
    const float* __restrict__ x = resolve_in(nullptr, x_id);
    int t = threadIdx.x;
    float s = 0.f, q = 0.f;
    for (int r = blockIdx.x; r < M; r += gridDim.x) {
        float v = x[(size_t)r * 256 + t];
        s += v;
        q += v * v;
    }
    g_part[blockIdx.x * 512 + t] = s;
    g_part[blockIdx.x * 512 + 256 + t] = q;
}

__global__ void glob_final(const float* __restrict__ w, const float* __restrict__ b,
                           const float* __restrict__ ms, int nb, int M) {
    int t = threadIdx.x;
    float s = 0.f, q = 0.f;
    for (int i = 0; i < nb; ++i) {
        s += g_part[i * 512 + t];
        q += g_part[i * 512 + 256 + t];
    }
    float mean = s / (float)M;
    float m2 = mean * ms[t];
    float var = q / (float)M - 2.f * m2 * mean + m2 * m2;
    float sc = w[t] * rsqrtf(var + EPSV);
    g_scale3[t] = sc;
    g_shift3[t] = b[t] - m2 * sc;
}

// ---------------- weight pre-conversion to tf32 (pair-permuted per 32-block) ----------------
__global__ void w_conv(const float* __restrict__ W, int n) {
    int i = blockIdx.x * 256 + threadIdx.x;
    if (i >= n) return;
    int out = (i & ~31) + kperm(i & 31);
    g_Wt[out] = f2tf32(W[i]);
}

// ---------------- fused norm/prelu tf32 GEMM (mma.sync, 128x256 CTA tile) ----------------
__global__ __launch_bounds__(512, 1)
void gemm_tc(const float* Ap, int A_id, const int* __restrict__ batch,
             int layer, int gstride, const float* __restrict__ alphaP,
             const float* __restrict__ bias,
             int res_id, float* outp, int out_id, int M, int N, int K) {
    extern __shared__ char dynraw[];
    char* base = (char*)(((uintptr_t)dynraw + 127) & ~(uintptr_t)127);
    unsigned* Asb[2] = {(unsigned*)base, (unsigned*)(base + A_TILE_BYTES)};
    unsigned* Bsb[2] = {(unsigned*)(base + 2 * A_TILE_BYTES),
                        (unsigned*)(base + 2 * A_TILE_BYTES + B_TILE_BYTES)};
    __shared__ int s_rowg[TM];

    const float* __restrict__ A = resolve_in(Ap, A_id);
    const float* __restrict__ scale = scale_tab(layer);
    const float* __restrict__ shift = shift_tab(layer);
    const float* res = res_id ? resolve_in(nullptr, res_id) : nullptr;
    float* out = resolve_out(outp, out_id);

    const int tid = threadIdx.x;
    const int lane = tid & 31;
    const int warp = tid >> 5;          // 0..15
    const int bm = blockIdx.y * TM;
    const int bn = blockIdx.x * TN;
    const bool use_prelu = (alphaP != nullptr);
    const float alpha = use_prelu ? *alphaP : 0.f;

    const uint32_t b0u = smem_u32(Bsb[0]);
    const uint32_t b1u = smem_u32(Bsb[1]);

    if (tid < TM) {
        int m = bm + tid;
        int g = batch[m < M ? m : (M - 1)];
        s_rowg[tid] = (g >= 0 && g < NGRAPH) ? g : 0;
    }
    __syncthreads();
    const bool uni = (s_rowg[0] == s_rowg[TM - 1]);
    const int g0 = s_rowg[0];

    // 16 warps: 4 (M) x 4 (N) grid of 32x64 warp tiles
    const int wm = (warp & 3) * 32;
    const int wn = (warp >> 2) * 64;
    const int qid = lane >> 2;
    const int tig = lane & 3;

    // A staging: 2 iters x 512 threads = 1024 slots = 128 rows x 8 float4
    float4 av[2];

    auto cpW = [&](int s) {
        const int kbase = s * BK;
        const uint32_t dstb = (s & 1) ? b1u : b0u;
#pragma unroll
        for (int it = 0; it < 4; ++it) {
            int idx = it * 512 + tid;          // 2048 slots = 256 rows x 8
            int row = idx >> 3;
            int kq = (idx & 7) * 4;            // permuted slot base (16B granule)
            int word = row * SAS_B + (kq ^ ((row & 3) << 3));
            cp16(dstb + word * 4, g_Wt + (size_t)(bn + row) * K + kbase + kq);
        }
    };

    auto fetchA = [&](int s) {
        const int kbase = s * BK;
#pragma unroll
        for (int it = 0; it < 2; ++it) {
            int idx = it * 512 + tid;
            int row = idx >> 3;
            int kq = (idx & 7) * 4;
            int rg = bm + row; if (rg >= M) rg = M - 1;
            float4 v = *reinterpret_cast<const float4*>(A + (size_t)rg * K + kbase + kq);
            int g = uni ? g0 : s_rowg[row];
            float4 sc = *reinterpret_cast<const float4*>(scale + (size_t)g * gstride + kbase + kq);
            float4 sh = *reinterpret_cast<const float4*>(shift + (size_t)g * gstride + kbase + kq);
            float4 o;
            o.x = fmaf(v.x, sc.x, sh.x);
            o.y = fmaf(v.y, sc.y, sh.y);
            o.z = fmaf(v.z, sc.z, sh.z);
            o.w = fmaf(v.w, sc.w, sh.w);
            if (use_prelu) {
                o.x = o.x >= 0.f ? o.x : alpha * o.x;
                o.y = o.y >= 0.f ? o.y : alpha * o.y;
                o.z = o.z >= 0.f ? o.z : alpha * o.z;
                o.w = o.w >= 0.f ? o.w : alpha * o.w;
            }
            av[it] = o;
        }
    };

    auto storeA = [&](int buf) {
#pragma unroll
        for (int it = 0; it < 2; ++it) {
            int idx = it * 512 + tid;
            int row = idx >> 3;
            int kq = (idx & 7) * 4;
            uint4 t;
            t.x = f2tf32(av[it].x); t.y = f2tf32(av[it].y);
            t.z = f2tf32(av[it].z); t.w = f2tf32(av[it].w);
            *reinterpret_cast<uint4*>(&Asb[buf][row * SAS_A + kq]) = t;
        }
    };

    float acc[2][8][4];
#pragma unroll
    for (int a = 0; a < 2; ++a)
#pragma unroll
        for (int b2 = 0; b2 < 8; ++b2)
#pragma unroll
            for (int c = 0; c < 4; ++c) acc[a][b2][c] = 0.f;

    auto compute = [&](int buf) {
        const unsigned* As = Asb[buf];
        const unsigned* Bs = Bsb[buf];
#pragma unroll
        for (int kk = 0; kk < 4; ++kk) {
            unsigned a[2][4];
#pragma unroll
            for (int mt = 0; mt < 2; ++mt) {
                int row = wm + mt * 16 + qid;
                a[mt][0] = As[row * SAS_A + kk * 8 + tig];
                a[mt][2] = As[row * SAS_A + kk * 8 + tig + 4];
                a[mt][1] = As[(row + 8) * SAS_A + kk * 8 + tig];
                a[mt][3] = As[(row + 8) * SAS_A + kk * 8 + tig + 4];
            }
            unsigned bf[8][2];
#pragma unroll
            for (int nt = 0; nt < 8; ++nt) {
                int col = wn + nt * 8 + qid;
                int word = col * SAS_B + ((kk * 8 + 2 * tig) ^ ((col & 3) << 3));
                uint2 bb = *reinterpret_cast<const uint2*>(Bs + word);
                bf[nt][0] = bb.x; bf[nt][1] = bb.y;
            }
#pragma unroll
            for (int mt = 0; mt < 2; ++mt)
#pragma unroll
                for (int nt = 0; nt < 8; ++nt) mma8(acc[mt][nt], a[mt], bf[nt]);
        }
    };

    // prologue
    cpW(0);
    CP_COMMIT();
    fetchA(0);
    storeA(0);
    CP_WAIT0();
    __syncthreads();

    const int KT = K / BK;
    for (int s = 0; s < KT; ++s) {
        if (s + 1 < KT) {
            cpW(s + 1);
            CP_COMMIT();
            fetchA(s + 1);
        }
        compute(s & 1);
        if (s + 1 < KT) storeA((s + 1) & 1);
        CP_WAIT0();
        __syncthreads();
    }

    // epilogue
#pragma unroll
    for (int mt = 0; mt < 2; ++mt) {
        int r0 = bm + wm + mt * 16 + qid;
        int r1 = r0 + 8;
#pragma unroll
        for (int nt = 0; nt < 8; ++nt) {
            int c = bn + wn + nt * 8 + tig * 2;
            float2 b2 = *reinterpret_cast<const float2*>(bias + c);
            if (r0 < M) {
                float v0 = acc[mt][nt][0] + b2.x;
                float v1 = acc[mt][nt][1] + b2.y;
                if (res) {
                    float2 rr = *reinterpret_cast<const float2*>(res + (size_t)r0 * N + c);
                    v0 = (v0 + rr.x) * 0.5f;
                    v1 = (v1 + rr.y) * 0.5f;
                }
                *reinterpret_cast<float2*>(out + (size_t)r0 * N + c) = make_float2(v0, v1);
            }
            if (r1 < M) {
                float v0 = acc[mt][nt][2] + b2.x;
                float v1 = acc[mt][nt][3] + b2.y;
                if (res) {
                    float2 rr = *reinterpret_cast<const float2*>(res + (size_t)r1 * N + c);
                    v0 = (v0 + rr.x) * 0.5f;
                    v1 = (v1 + rr.y) * 0.5f;
                }
                *reinterpret_cast<float2*>(out + (size_t)r1 * N + c) = make_float2(v0, v1);
            }
        }
    }
}

// ---------------- launch ----------------
extern "C" void kernel_launch(void* const* d_in, const int* in_sizes, int n_in,
                              void* d_out, int out_size) {
    const float* x = (const float*)d_in[0];
    const int* batch = (const int*)d_in[1];
    const float* gn1_w = (const float*)d_in[2];
    const float* gn1_b = (const float*)d_in[3];
    const float* gn1_ms = (const float*)d_in[4];
    const float* gn2_w = (const float*)d_in[5];
    const float* gn2_b = (const float*)d_in[6];
    const float* gn2_ms = (const float*)d_in[7];
    const float* gn3_w = (const float*)d_in[8];
    const float* gn3_b = (const float*)d_in[9];
    const float* gn3_ms = (const float*)d_in[10];
    const float* gn4_w = (const float*)d_in[11];
    const float* gn4_b = (const float*)d_in[12];
    const float* gn4_ms = (const float*)d_in[13];
    const float* gn5_w = (const float*)d_in[14];
    const float* gn5_b = (const float*)d_in[15];
    const float* gn5_ms = (const float*)d_in[16];
    const float* lin1_W = (const float*)d_in[17];
    const float* lin1_b = (const float*)d_in[18];
    const float* lin2_W = (const float*)d_in[19];
    const float* lin2_b = (const float*)d_in[20];
    const float* lin3_W = (const float*)d_in[21];
    const float* lin3_b = (const float*)d_in[22];
    const float* lin4_W = (const float*)d_in[23];
    const float* lin4_b = (const float*)d_in[24];
    const float* lin5_W = (const float*)d_in[25];
    const float* lin5_b = (const float*)d_in[26];
    const float* a2 = (const float*)d_in[27];
    const float* a3 = (const float*)d_in[28];
    const float* a4 = (const float*)d_in[29];
    const float* a5 = (const float*)d_in[30];

    const int M = in_sizes[0] / 512;

    static bool attr_done = false;
    if (!attr_done) {
        cudaFuncSetAttribute(gemm_tc, cudaFuncAttributeMaxDynamicSharedMemorySize, DYN_SMEM);
        attr_done = true;
    }

    seg_bounds_init<<<1, NGRAPH>>>();
    seg_bounds<<<(M + 255) / 256, 256>>>(batch, M);

    const int gy = (M + TM - 1) / TM;

    // layer 1: gn1 -> lin1   (x -> s1)
    seg_stats_part<<<dim3(NGRAPH, 4), 512>>>(x, 0, 512);
    seg_stats_final<<<NGRAPH, 512>>>(gn1_w, gn1_b, gn1_ms, 1, 512);
    w_conv<<<512, 256>>>(lin1_W, 256 * 512);
    gemm_tc<<<dim3(1, gy), 512, DYN_SMEM>>>(x, 0, batch, 1, 512, nullptr,
                                            lin1_b, 0, nullptr, 1, M, 256, 512);

    // layer 2: gn2 -> prelu -> lin2   (s1 -> s2)
    seg_stats_part<<<dim3(NGRAPH, 4), 256>>>(nullptr, 1, 256);
    seg_stats_final<<<NGRAPH, 256>>>(gn2_w, gn2_b, gn2_ms, 2, 256);
    w_conv<<<256, 256>>>(lin2_W, 256 * 256);
    gemm_tc<<<dim3(1, gy), 512, DYN_SMEM>>>(nullptr, 1, batch, 2, 256, a2,
                                            lin2_b, 0, nullptr, 2, M, 256, 256);

    // layer 3: gn3 (global) -> prelu -> lin3, (h + x1)/2   (s2 -> s1, res s1)
    glob_partial<<<512, 256>>>(2, M);
    glob_final<<<1, 256>>>(gn3_w, gn3_b, gn3_ms, 512, M);
    w_conv<<<256, 256>>>(lin3_W, 256 * 256);
    gemm_tc<<<dim3(1, gy), 512, DYN_SMEM>>>(nullptr, 2, batch, 3, 0, a3,
                                            lin3_b, 1, nullptr, 1, M, 256, 256);

    // layer 4: gn4 -> prelu -> lin4, (h + x2)/2   (s1 -> s2, res s1)
    seg_stats_part<<<dim3(NGRAPH, 4), 256>>>(nullptr, 1, 256);
    seg_stats_final<<<NGRAPH, 256>>>(gn4_w, gn4_b, gn4_ms, 4, 256);
    w_conv<<<256, 256>>>(lin4_W, 256 * 256);
    gemm_tc<<<dim3(1, gy), 512, DYN_SMEM>>>(nullptr, 1, batch, 4, 256, a4,
                                            lin4_b, 1, nullptr, 2, M, 256, 256);

    // layer 5: gn5 -> prelu -> lin5   (s2 -> d_out)
    seg_stats_part<<<dim3(NGRAPH, 4), 256>>>(nullptr, 2, 256);
    seg_stats_final<<<NGRAPH, 256>>>(gn5_w, gn5_b, gn5_ms, 5, 256);
    w_conv<<<512, 256>>>(lin5_W, 512 * 256);
    gemm_tc<<<dim3(2, gy), 512, DYN_SMEM>>>(nullptr, 2, batch, 5, 256, a5,
                                            lin5_b, 0, (float*)d_out, 0, M, 512, 256);
}

// round 16
// speedup vs baseline: 1.1019x; 1.1019x over previous
#include <cuda_runtime.h>
#include <cstdint>

#define EPSV 1e-5f
#define NGRAPH 256
#define MAXM 100096

#define TM 128
#define TN 128
#define BK 32
#define SAS 36                      // padded row stride in words
#define TILE_BYTES (128 * SAS * 4)  // 18432
#define DYN_SMEM (4 * TILE_BYTES + 256)

// ---------------- scratch (device globals; no allocations) ----------------
__device__ int g_start[NGRAPH];
__device__ int g_end[NGRAPH];
__device__ __align__(16) float g_scale1[NGRAPH * 512];
__device__ __align__(16) float g_shift1[NGRAPH * 512];
__device__ __align__(16) float g_scale2[NGRAPH * 256];
__device__ __align__(16) float g_shift2[NGRAPH * 256];
__device__ __align__(16) float g_scale3[256];
__device__ __align__(16) float g_shift3[256];
__device__ __align__(16) float g_scale4[NGRAPH * 256];
__device__ __align__(16) float g_shift4[NGRAPH * 256];
__device__ __align__(16) float g_scale5[NGRAPH * 256];
__device__ __align__(16) float g_shift5[NGRAPH * 256];
__device__ __align__(16) float g_part2[NGRAPH * 4 * 1024];
__device__ __align__(16) float g_ssum[NGRAPH * 256];   // fused epilogue stats: sum
__device__ __align__(16) float g_ssq[NGRAPH * 256];    // fused epilogue stats: sum of squares
__device__ __align__(16) unsigned g_Wt[512 * 256];     // tf32 weights
__device__ __align__(16) float g_s1[(size_t)MAXM * 256];
__device__ __align__(16) float g_s2[(size_t)MAXM * 256];

__device__ __forceinline__ const float* resolve_in(const float* p, int id) {
    if (id == 1) return g_s1;
    if (id == 2) return g_s2;
    return p;
}
__device__ __forceinline__ float* resolve_out(float* p, int id) {
    if (id == 1) return g_s1;
    if (id == 2) return g_s2;
    return p;
}
__device__ __forceinline__ const float* scale_tab(int layer) {
    switch (layer) {
        case 1: return g_scale1;
        case 2: return g_scale2;
        case 3: return g_scale3;
        case 4: return g_scale4;
        default: return g_scale5;
    }
}
__device__ __forceinline__ const float* shift_tab(int layer) {
    switch (layer) {
        case 1: return g_shift1;
        case 2: return g_shift2;
        case 3: return g_shift3;
        case 4: return g_shift4;
        default: return g_shift5;
    }
}
__device__ __forceinline__ float* scale_tab_w(int layer) {
    switch (layer) {
        case 1: return g_scale1;
        case 2: return g_scale2;
        case 3: return g_scale3;
        case 4: return g_scale4;
        default: return g_scale5;
    }
}
__device__ __forceinline__ float* shift_tab_w(int layer) {
    switch (layer) {
        case 1: return g_shift1;
        case 2: return g_shift2;
        case 3: return g_shift3;
        case 4: return g_shift4;
        default: return g_shift5;
    }
}

// ---------------- helpers ----------------
__device__ __forceinline__ uint32_t smem_u32(const void* p) {
    uint32_t a;
    asm("{ .reg .u64 t; cvta.to.shared.u64 t, %1; cvt.u32.u64 %0, t; }" : "=r"(a) : "l"(p));
    return a;
}
__device__ __forceinline__ unsigned f2tf32(float f) {
    unsigned r;
    asm("cvt.rna.tf32.f32 %0, %1;" : "=r"(r) : "f"(f));
    return r;
}
__device__ __forceinline__ void mma8(float c[4], const unsigned a[4], const unsigned b[2]) {
    asm volatile(
        "mma.sync.aligned.m16n8k8.row.col.f32.tf32.tf32.f32 "
        "{%0,%1,%2,%3}, {%4,%5,%6,%7}, {%8,%9}, {%0,%1,%2,%3};\n"
        : "+f"(c[0]), "+f"(c[1]), "+f"(c[2]), "+f"(c[3])
        : "r"(a[0]), "r"(a[1]), "r"(a[2]), "r"(a[3]), "r"(b[0]), "r"(b[1]));
}
__device__ __forceinline__ void cp16(uint32_t dst, const void* src) {
    asm volatile("cp.async.cg.shared.global [%0], [%1], 16;" :: "r"(dst), "l"(src));
}
#define CP_COMMIT() asm volatile("cp.async.commit_group;" ::: "memory")
#define CP_WAIT0()  asm volatile("cp.async.wait_group 0;" ::: "memory")

// ---------------- segment bounds ----------------
__global__ void seg_bounds_init() {
    int t = threadIdx.x;
    if (t < NGRAPH) { g_start[t] = 0; g_end[t] = 0; }
}

__global__ void seg_bounds(const int* __restrict__ batch, int n) {
    int i = blockIdx.x * blockDim.x + threadIdx.x;
    if (i >= n) return;
    int g = batch[i];
    if (g < 0 || g >= NGRAPH) return;
    if (i == 0 || batch[i - 1] != g) g_start[g] = i;
    if (i == n - 1 || batch[i + 1] != g) g_end[g] = i + 1;
}

// ---------------- layer-1 stats over x: 4-way split partial + combine ----------------
__global__ void seg_stats_part(const float* __restrict__ x, int dim) {
    int g = blockIdx.x, part = blockIdx.y, t = threadIdx.x;
    int s0 = g_start[g], e0 = g_end[g];
    int len = e0 - s0;
    int chunk = (len + 3) >> 2;
    int r0 = s0 + part * chunk;
    int r1 = r0 + chunk; if (r1 > e0) r1 = e0;
    float s = 0.f, q = 0.f;
    for (int r = r0; r < r1; ++r) {
        float v = x[(size_t)r * dim + t];
        s += v;
        q += v * v;
    }
    size_t base = ((size_t)(g * 4 + part)) * 1024;
    g_part2[base + t] = s;
    g_part2[base + 512 + t] = q;
}

__global__ void seg_stats_final(const float* __restrict__ w, const float* __restrict__ b,
                                const float* __restrict__ ms, int layer, int dim) {
    float* __restrict__ scale = scale_tab_w(layer);
    float* __restrict__ shift = shift_tab_w(layer);
    int g = blockIdx.x, t = threadIdx.x;
    float s = 0.f, q = 0.f;
#pragma unroll
    for (int p = 0; p < 4; ++p) {
        size_t base = ((size_t)(g * 4 + p)) * 1024;
        s += g_part2[base + t];
        q += g_part2[base + 512 + t];
    }
    float cnt = fmaxf((float)(g_end[g] - g_start[g]), 1.f);
    float mean = s / cnt;
    float m2 = mean * ms[t];
    float var = q / cnt - 2.f * m2 * mean + m2 * m2;
    float sc = w[t] * rsqrtf(var + EPSV);
    scale[(size_t)g * dim + t] = sc;
    shift[(size_t)g * dim + t] = b[t] - m2 * sc;
}

// ---------------- stats finalize from fused epilogue sums (dim 256) ----------------
__global__ void seg_stats_final2(const float* __restrict__ w, const float* __restrict__ b,
                                 const float* __restrict__ ms, int layer) {
    float* __restrict__ scale = scale_tab_w(layer);
    float* __restrict__ shift = shift_tab_w(layer);
    int g = blockIdx.x, t = threadIdx.x;
    float s = g_ssum[g * 256 + t];
    float q = g_ssq[g * 256 + t];
    float cnt = fmaxf((float)(g_end[g] - g_start[g]), 1.f);
    float mean = s / cnt;
    float m2 = mean * ms[t];
    float var = q / cnt - 2.f * m2 * mean + m2 * m2;
    float sc = w[t] * rsqrtf(var + EPSV);
    scale[(size_t)g * 256 + t] = sc;
    shift[(size_t)g * 256 + t] = b[t] - m2 * sc;
}

// global stats (gn3): sum fused per-graph sums over all graphs
__global__ void glob_final2(const float* __restrict__ w, const float* __restrict__ b,
                            const float* __restrict__ ms, int M) {
    int t = threadIdx.x;
    float s = 0.f, q = 0.f;
    for (int g = 0; g < NGRAPH; ++g) {
        s += g_ssum[g * 256 + t];
        q += g_ssq[g * 256 + t];
    }
    float mean = s / (float)M;
    float m2 = mean * ms[t];
    float var = q / (float)M - 2.f * m2 * mean + m2 * m2;
    float sc = w[t] * rsqrtf(var + EPSV);
    g_scale3[t] = sc;
    g_shift3[t] = b[t] - m2 * sc;
}

// ---------------- weight pre-conversion to tf32 (+ optional stats zeroing) ----------------
__global__ void w_conv(const float* __restrict__ W, int n, int zstats) {
    int i = blockIdx.x * 256 + threadIdx.x;
    if (i < n) g_Wt[i] = f2tf32(W[i]);
    if (zstats && i < NGRAPH * 256) { g_ssum[i] = 0.f; g_ssq[i] = 0.f; }
}

// ---------------- fused norm/prelu tf32 GEMM + fused next-layer stats ----------------
__global__ __launch_bounds__(256, 2)
void gemm_tc(const float* Ap, int A_id, const int* __restrict__ batch,
             int layer, int gstride, const float* __restrict__ alphaP,
             const float* __restrict__ bias,
             int res_id, float* outp, int out_id, int stats_on,
             int M, int N, int K) {
    extern __shared__ char dynraw[];
    char* base = (char*)(((uintptr_t)dynraw + 127) & ~(uintptr_t)127);
    unsigned* Asb[2] = {(unsigned*)base, (unsigned*)(base + TILE_BYTES)};
    unsigned* Bsb[2] = {(unsigned*)(base + 2 * TILE_BYTES), (unsigned*)(base + 3 * TILE_BYTES)};
    __shared__ int s_rowg[TM];

    const float* __restrict__ A = resolve_in(Ap, A_id);
    const float* __restrict__ scale = scale_tab(layer);
    const float* __restrict__ shift = shift_tab(layer);
    const float* res = res_id ? resolve_in(nullptr, res_id) : nullptr;
    float* out = resolve_out(outp, out_id);

    const int tid = threadIdx.x;
    const int lane = tid & 31;
    const int warp = tid >> 5;
    const int bm = blockIdx.y * TM;
    const int bn = blockIdx.x * TN;
    const bool use_prelu = (alphaP != nullptr);
    const float alpha = use_prelu ? *alphaP : 0.f;

    const uint32_t b0u = smem_u32(Bsb[0]);
    const uint32_t b1u = smem_u32(Bsb[1]);

    if (tid < TM) {
        int m = bm + tid;
        int g = batch[m < M ? m : (M - 1)];
        s_rowg[tid] = (g >= 0 && g < NGRAPH) ? g : 0;
    }
    __syncthreads();
    const bool uni = (s_rowg[0] == s_rowg[TM - 1]);
    const int g0 = s_rowg[0];

    const int wm = (warp >> 1) * 32;
    const int wn = (warp & 1) * 64;
    const int qid = lane >> 2;
    const int tig = lane & 3;

    float4 av[4];

    auto cpW = [&](int s) {
        const int kbase = s * BK;
        const uint32_t dstb = (s & 1) ? b1u : b0u;
#pragma unroll
        for (int it = 0; it < 4; ++it) {
            int idx = it * 256 + tid;
            int row = idx >> 3;
            int kq = (idx & 7) * 4;
            cp16(dstb + (row * SAS + kq) * 4, g_Wt + (size_t)(bn + row) * K + kbase + kq);
        }
    };

    auto fetchA = [&](int s) {
        const int kbase = s * BK;
#pragma unroll
        for (int it = 0; it < 4; ++it) {
            int idx = it * 256 + tid;
            int row = idx >> 3;
            int kq = (idx & 7) * 4;
            int rg = bm + row; if (rg >= M) rg = M - 1;
            float4 v = *reinterpret_cast<const float4*>(A + (size_t)rg * K + kbase + kq);
            int g = uni ? g0 : s_rowg[row];
            float4 sc = *reinterpret_cast<const float4*>(scale + (size_t)g * gstride + kbase + kq);
            float4 sh = *reinterpret_cast<const float4*>(shift + (size_t)g * gstride + kbase + kq);
            float4 o;
            o.x = fmaf(v.x, sc.x, sh.x);
            o.y = fmaf(v.y, sc.y, sh.y);
            o.z = fmaf(v.z, sc.z, sh.z);
            o.w = fmaf(v.w, sc.w, sh.w);
            if (use_prelu) {
                o.x = o.x >= 0.f ? o.x : alpha * o.x;
                o.y = o.y >= 0.f ? o.y : alpha * o.y;
                o.z = o.z >= 0.f ? o.z : alpha * o.z;
                o.w = o.w >= 0.f ? o.w : alpha * o.w;
            }
            av[it] = o;
        }
    };

    auto storeA = [&](int buf) {
#pragma unroll
        for (int it = 0; it < 4; ++it) {
            int idx = it * 256 + tid;
            int row = idx >> 3;
            int kq = (idx & 7) * 4;
            uint4 t;
            t.x = f2tf32(av[it].x); t.y = f2tf32(av[it].y);
            t.z = f2tf32(av[it].z); t.w = f2tf32(av[it].w);
            *reinterpret_cast<uint4*>(&Asb[buf][row * SAS + kq]) = t;
        }
    };

    float acc[2][8][4];
#pragma unroll
    for (int a = 0; a < 2; ++a)
#pragma unroll
        for (int b2 = 0; b2 < 8; ++b2)
#pragma unroll
            for (int c = 0; c < 4; ++c) acc[a][b2][c] = 0.f;

    auto compute = [&](int buf) {
        const unsigned* As = Asb[buf];
        const unsigned* Bs = Bsb[buf];
#pragma unroll
        for (int kk = 0; kk < 4; ++kk) {
            unsigned a[2][4];
#pragma unroll
            for (int mt = 0; mt < 2; ++mt) {
                int row = wm + mt * 16 + qid;
                a[mt][0] = As[row * SAS + kk * 8 + tig];
                a[mt][2] = As[row * SAS + kk * 8 + tig + 4];
                a[mt][1] = As[(row + 8) * SAS + kk * 8 + tig];
                a[mt][3] = As[(row + 8) * SAS + kk * 8 + tig + 4];
            }
            unsigned bf[8][2];
#pragma unroll
            for (int nt = 0; nt < 8; ++nt) {
                int col = wn + nt * 8 + qid;
                bf[nt][0] = Bs[col * SAS + kk * 8 + tig];
                bf[nt][1] = Bs[col * SAS + kk * 8 + tig + 4];
            }
#pragma unroll
            for (int mt = 0; mt < 2; ++mt)
#pragma unroll
                for (int nt = 0; nt < 8; ++nt) mma8(acc[mt][nt], a[mt], bf[nt]);
        }
    };

    // prologue
    cpW(0);
    CP_COMMIT();
    fetchA(0);
    storeA(0);
    CP_WAIT0();
    __syncthreads();

    const int KT = K / BK;
    for (int s = 0; s < KT; ++s) {
        if (s + 1 < KT) {
            cpW(s + 1);
            CP_COMMIT();
            fetchA(s + 1);
        }
        compute(s & 1);
        if (s + 1 < KT) storeA((s + 1) & 1);
        CP_WAIT0();
        __syncthreads();
    }

    // ---- epilogue (+ fused stats for next layer's GraphNorm) ----
    const int gA = s_rowg[wm];
    const int gB = s_rowg[wm + 31];
#pragma unroll
    for (int nt = 0; nt < 8; ++nt) {
        int c = bn + wn + nt * 8 + tig * 2;
        float2 b2 = *reinterpret_cast<const float2*>(bias + c);
        float sA0 = 0.f, sA1 = 0.f, qA0 = 0.f, qA1 = 0.f;
        float sB0 = 0.f, sB1 = 0.f, qB0 = 0.f, qB1 = 0.f;
#pragma unroll
        for (int mt = 0; mt < 2; ++mt) {
            int r0 = bm + wm + mt * 16 + qid;
            int r1 = r0 + 8;
            if (r0 < M) {
                float v0 = acc[mt][nt][0] + b2.x;
                float v1 = acc[mt][nt][1] + b2.y;
                if (res) {
                    float2 rr = *reinterpret_cast<const float2*>(res + (size_t)r0 * N + c);
                    v0 = (v0 + rr.x) * 0.5f;
                    v1 = (v1 + rr.y) * 0.5f;
                }
                *reinterpret_cast<float2*>(out + (size_t)r0 * N + c) = make_float2(v0, v1);
                if (stats_on) {
                    int g = s_rowg[r0 - bm];
                    if (g == gA) { sA0 += v0; qA0 += v0 * v0; sA1 += v1; qA1 += v1 * v1; }
                    else if (g == gB) { sB0 += v0; qB0 += v0 * v0; sB1 += v1; qB1 += v1 * v1; }
                    else {
                        atomicAdd(&g_ssum[g * 256 + c], v0);  atomicAdd(&g_ssq[g * 256 + c], v0 * v0);
                        atomicAdd(&g_ssum[g * 256 + c + 1], v1); atomicAdd(&g_ssq[g * 256 + c + 1], v1 * v1);
                    }
                }
            }
            if (r1 < M) {
                float v0 = acc[mt][nt][2] + b2.x;
                float v1 = acc[mt][nt][3] + b2.y;
                if (res) {
                    float2 rr = *reinterpret_cast<const float2*>(res + (size_t)r1 * N + c);
                    v0 = (v0 + rr.x) * 0.5f;
                    v1 = (v1 + rr.y) * 0.5f;
                }
                *reinterpret_cast<float2*>(out + (size_t)r1 * N + c) = make_float2(v0, v1);
                if (stats_on) {
                    int g = s_rowg[r1 - bm];
                    if (g == gA) { sA0 += v0; qA0 += v0 * v0; sA1 += v1; qA1 += v1 * v1; }
                    else if (g == gB) { sB0 += v0; qB0 += v0 * v0; sB1 += v1; qB1 += v1 * v1; }
                    else {
                        atomicAdd(&g_ssum[g * 256 + c], v0);  atomicAdd(&g_ssq[g * 256 + c], v0 * v0);
                        atomicAdd(&g_ssum[g * 256 + c + 1], v1); atomicAdd(&g_ssq[g * 256 + c + 1], v1 * v1);
                    }
                }
            }
        }
        if (stats_on) {
            // butterfly-reduce over the 8 qid lanes (strides 4, 8, 16)
#pragma unroll
            for (int st = 4; st <= 16; st <<= 1) {
                sA0 += __shfl_xor_sync(0xffffffffu, sA0, st);
                sA1 += __shfl_xor_sync(0xffffffffu, sA1, st);
                qA0 += __shfl_xor_sync(0xffffffffu, qA0, st);
                qA1 += __shfl_xor_sync(0xffffffffu, qA1, st);
                if (gB != gA) {
                    sB0 += __shfl_xor_sync(0xffffffffu, sB0, st);
                    sB1 += __shfl_xor_sync(0xffffffffu, sB1, st);
                    qB0 += __shfl_xor_sync(0xffffffffu, qB0, st);
                    qB1 += __shfl_xor_sync(0xffffffffu, qB1, st);
                }
            }
            if (lane < 4) {  // qid == 0, lane == tig
                atomicAdd(&g_ssum[gA * 256 + c], sA0);     atomicAdd(&g_ssq[gA * 256 + c], qA0);
                atomicAdd(&g_ssum[gA * 256 + c + 1], sA1); atomicAdd(&g_ssq[gA * 256 + c + 1], qA1);
                if (gB != gA) {
                    atomicAdd(&g_ssum[gB * 256 + c], sB0);     atomicAdd(&g_ssq[gB * 256 + c], qB0);
                    atomicAdd(&g_ssum[gB * 256 + c + 1], sB1); atomicAdd(&g_ssq[gB * 256 + c + 1], qB1);
                }
            }
        }
    }
}

// ---------------- launch ----------------
extern "C" void kernel_launch(void* const* d_in, const int* in_sizes, int n_in,
                              void* d_out, int out_size) {
    const float* x = (const float*)d_in[0];
    const int* batch = (const int*)d_in[1];
    const float* gn1_w = (const float*)d_in[2];
    const float* gn1_b = (const float*)d_in[3];
    const float* gn1_ms = (const float*)d_in[4];
    const float* gn2_w = (const float*)d_in[5];
    const float* gn2_b = (const float*)d_in[6];
    const float* gn2_ms = (const float*)d_in[7];
    const float* gn3_w = (const float*)d_in[8];
    const float* gn3_b = (const float*)d_in[9];
    const float* gn3_ms = (const float*)d_in[10];
    const float* gn4_w = (const float*)d_in[11];
    const float* gn4_b = (const float*)d_in[12];
    const float* gn4_ms = (const float*)d_in[13];
    const float* gn5_w = (const float*)d_in[14];
    const float* gn5_b = (const float*)d_in[15];
    const float* gn5_ms = (const float*)d_in[16];
    const float* lin1_W = (const float*)d_in[17];
    const float* lin1_b = (const float*)d_in[18];
    const float* lin2_W = (const float*)d_in[19];
    const float* lin2_b = (const float*)d_in[20];
    const float* lin3_W = (const float*)d_in[21];
    const float* lin3_b = (const float*)d_in[22];
    const float* lin4_W = (const float*)d_in[23];
    const float* lin4_b = (const float*)d_in[24];
    const float* lin5_W = (const float*)d_in[25];
    const float* lin5_b = (const float*)d_in[26];
    const float* a2 = (const float*)d_in[27];
    const float* a3 = (const float*)d_in[28];
    const float* a4 = (const float*)d_in[29];
    const float* a5 = (const float*)d_in[30];

    const int M = in_sizes[0] / 512;

    static bool attr_done = false;
    if (!attr_done) {
        cudaFuncSetAttribute(gemm_tc, cudaFuncAttributeMaxDynamicSharedMemorySize, DYN_SMEM);
        attr_done = true;
    }

    seg_bounds_init<<<1, NGRAPH>>>();
    seg_bounds<<<(M + 255) / 256, 256>>>(batch, M);

    const int gy = (M + TM - 1) / TM;

    // layer 1: gn1 (stats over x) -> lin1   (x -> s1); epilogue accumulates gn2 stats
    seg_stats_part<<<dim3(NGRAPH, 4), 512>>>(x, 512);
    seg_stats_final<<<NGRAPH, 512>>>(gn1_w, gn1_b, gn1_ms, 1, 512);
    w_conv<<<512, 256>>>(lin1_W, 256 * 512, 1);
    gemm_tc<<<dim3(2, gy), 256, DYN_SMEM>>>(x, 0, batch, 1, 512, nullptr,
                                            lin1_b, 0, nullptr, 1, 1, M, 256, 512);

    // layer 2: gn2 (fused sums) -> prelu -> lin2   (s1 -> s2); epilogue accumulates gn3 data
    seg_stats_final2<<<NGRAPH, 256>>>(gn2_w, gn2_b, gn2_ms, 2);
    w_conv<<<256, 256>>>(lin2_W, 256 * 256, 1);
    gemm_tc<<<dim3(2, gy), 256, DYN_SMEM>>>(nullptr, 1, batch, 2, 256, a2,
                                            lin2_b, 0, nullptr, 2, 1, M, 256, 256);

    // layer 3: gn3 (global, from fused sums) -> prelu -> lin3, (h + x1)/2  (s2 -> s1, res s1)
    glob_final2<<<1, 256>>>(gn3_w, gn3_b, gn3_ms, M);
    w_conv<<<256, 256>>>(lin3_W, 256 * 256, 1);
    gemm_tc<<<dim3(2, gy), 256, DYN_SMEM>>>(nullptr, 2, batch, 3, 0, a3,
                                            lin3_b, 1, nullptr, 1, 1, M, 256, 256);

    // layer 4: gn4 (fused sums) -> prelu -> lin4, (h + x2)/2   (s1 -> s2, res s1)
    seg_stats_final2<<<NGRAPH, 256>>>(gn4_w, gn4_b, gn4_ms, 4);
    w_conv<<<256, 256>>>(lin4_W, 256 * 256, 1);
    gemm_tc<<<dim3(2, gy), 256, DYN_SMEM>>>(nullptr, 1, batch, 4, 256, a4,
                                            lin4_b, 1, nullptr, 2, 1, M, 256, 256);

    // layer 5: gn5 (fused sums) -> prelu -> lin5   (s2 -> d_out)
    seg_stats_final2<<<NGRAPH, 256>>>(gn5_w, gn5_b, gn5_ms, 5);
    w_conv<<<512, 256>>>(lin5_W, 512 * 256, 0);
    gemm_tc<<<dim3(4, gy), 256, DYN_SMEM>>>(nullptr, 2, batch, 5, 256, a5,
                                            lin5_b, 0, (float*)d_out, 0, 0, M, 512, 256);
}